// round 15
// baseline (speedup 1.0000x reference)
#include <cuda_runtime.h>
#include <math.h>

// Problem shape (fixed by setup_inputs): pred/target (32,1,1024,1024) f32.
#define Wd   1024
#define Hd   1024
#define Bd   32
#define RPB  16                       // rows per block (R8-proven granularity)
#define GRPS (Hd / RPB)               // 64 row-groups per image
#define NBLK (Bd * GRPS)              // 2048 blocks
#define NTHR 256                      // 8 warps * 128 cols = 1024 cols

#define FULLM 0xFFFFFFFFu
#define NLN2  (-0.69314718055994530942f)

__device__ float        g_partials[NBLK];
__device__ unsigned int g_ticket;     // zero-init; reset by last block

__device__ __forceinline__ float4 ldv(const float* p) {
    return *reinterpret_cast<const float4*>(p);
}

// Per-row contribution: Sum_i w_i * log2(1-|t_i-p_i|), w_i = 1+2*b_i.
// Binary mask: 3x3-window sum S in [0,9]; boundary b = min(S, 9-S, 1).
// Border rows/cols handled by DUPLICATING the edge cell (clamp), which
// preserves S==0 <=> all-zero and S==9 <=> all-one exactly.
// haloSum: vertical 3-sum of this lane's halo column (lane 0 = left neighbor
// col, lane 31 = right neighbor col). The halo ADDRESS is clamped into the
// image, so at the image border haloSum equals the thread's own edge colsum
// (exactly the duplicate-edge identity) -> no select needed.
__device__ __forceinline__ float row_loss(
    const float4 c, const float4 t, const float4 p,
    float haloSum, int lane)
{
    float l = __shfl_up_sync(FULLM, c.w, 1);
    float r = __shfl_down_sync(FULLM, c.x, 1);
    if (lane == 0)  l = haloSum;
    if (lane == 31) r = haloSum;

    const float S0 = l   + c.x + c.y;
    const float S1 = c.x + c.y + c.z;
    const float S2 = c.y + c.z + c.w;
    const float S3 = c.z + c.w + r;

    const float b0 = fminf(fminf(S0, 9.0f - S0), 1.0f);
    const float b1 = fminf(fminf(S1, 9.0f - S1), 1.0f);
    const float b2 = fminf(fminf(S2, 9.0f - S2), 1.0f);
    const float b3 = fminf(fminf(S3, 9.0f - S3), 1.0f);

    // arg = 1-|t-p| == (t ? p : 1-p) exactly; pred in (1e-6, 1-1e-6) => arg>0.
    float s;
    s  = fmaf(2.0f, b0, 1.0f) * __log2f(1.0f - fabsf(t.x - p.x));
    s += fmaf(2.0f, b1, 1.0f) * __log2f(1.0f - fabsf(t.y - p.y));
    s += fmaf(2.0f, b2, 1.0f) * __log2f(1.0f - fabsf(t.z - p.z));
    s += fmaf(2.0f, b3, 1.0f) * __log2f(1.0f - fabsf(t.w - p.w));
    return s;
}

__global__ __launch_bounds__(NTHR, 6)
void bab_fused(const float* __restrict__ pred, const float* __restrict__ target,
               float* __restrict__ out)
{
    const int tid  = threadIdx.x;
    const int lane = tid & 31;
    const int warp = tid >> 5;

    const int grp = blockIdx.x;
    const int img = grp / GRPS;
    const int y0  = (grp % GRPS) * RPB;

    const int x0 = warp * 128 + lane * 4;     // this thread's 4 columns

    // Merged halo: lane 0 -> left neighbor col, lane 31 -> right neighbor col.
    // Address clamped into the image: border lanes read their own edge column,
    // which IS the duplicate-edge identity value.
    int xH = (lane == 0) ? (warp * 128 - 1) : (warp * 128 + 128);
    xH = (xH < 0) ? 0 : ((xH > Wd - 1) ? (Wd - 1) : xH);

    const float* __restrict__ tBase = target + (size_t)img * Hd * Wd + (size_t)y0 * Wd;
    const float* __restrict__ pBase = pred   + (size_t)img * Hd * Wd + (size_t)y0 * Wd;

    // Rolling pointers (bumped by 2*Wd per iteration; in-loop offsets are
    // compile-time immediates -> 1 LDG each, no per-load IMAD.WIDE).
    const float* tRow  = tBase + x0;
    const float* pRow  = pBase + x0;
    const float* tHalo = tBase + xH;

    // prev row: y0-1, clamped to y0 at the top border (duplicate row).
    const int prevOff = (y0 > 0) ? -Wd : 0;

    float4 cur  = ldv(tRow);
    float4 prev = ldv(tRow + prevOff);
    float curH  = tHalo[0];
    float prevH = tHalo[prevOff];

    float acc = 0.0f;

    // 7 unconditional 2-row iterations (rows y0..y0+13): y+2 always < Hd here
    // because the only possible clamp is at the very last row of the image.
    #pragma unroll
    for (int it = 0; it < RPB / 2 - 1; ++it) {
        const float4 nextA = ldv(tRow + Wd);
        const float4 nextB = ldv(tRow + 2 * Wd);
        const float4 pA    = ldv(pRow);
        const float4 pB    = ldv(pRow + Wd);
        const float nextAH = tHalo[Wd];
        const float nextBH = tHalo[2 * Wd];

        // Pairwise-shared vertical sums.
        float4 ps;
        ps.x = cur.x + nextA.x;  ps.y = cur.y + nextA.y;
        ps.z = cur.z + nextA.z;  ps.w = cur.w + nextA.w;

        float4 cA, cB;
        cA.x = prev.x + ps.x;  cB.x = ps.x + nextB.x;
        cA.y = prev.y + ps.y;  cB.y = ps.y + nextB.y;
        cA.z = prev.z + ps.z;  cB.z = ps.z + nextB.z;
        cA.w = prev.w + ps.w;  cB.w = ps.w + nextB.w;

        const float hsA = prevH + curH + nextAH;
        const float hsB = curH + nextAH + nextBH;

        acc += row_loss(cA, cur,   pA, hsA, lane);
        acc += row_loss(cB, nextA, pB, hsB, lane);

        prev  = nextA;  cur  = nextB;
        prevH = nextAH; curH = nextBH;

        tRow  += 2 * Wd;
        pRow  += 2 * Wd;
        tHalo += 2 * Wd;
    }

    // Final 2-row iteration (rows y0+14, y0+15): the y+2 row exists unless
    // this is the last row-group of the image; then duplicate the y+1 row.
    {
        const int offB = (y0 + RPB < Hd) ? (2 * Wd) : Wd;

        const float4 nextA = ldv(tRow + Wd);
        const float4 nextB = ldv(tRow + offB);
        const float4 pA    = ldv(pRow);
        const float4 pB    = ldv(pRow + Wd);
        const float nextAH = tHalo[Wd];
        const float nextBH = tHalo[offB];

        float4 ps;
        ps.x = cur.x + nextA.x;  ps.y = cur.y + nextA.y;
        ps.z = cur.z + nextA.z;  ps.w = cur.w + nextA.w;

        float4 cA, cB;
        cA.x = prev.x + ps.x;  cB.x = ps.x + nextB.x;
        cA.y = prev.y + ps.y;  cB.y = ps.y + nextB.y;
        cA.z = prev.z + ps.z;  cB.z = ps.z + nextB.z;
        cA.w = prev.w + ps.w;  cB.w = ps.w + nextB.w;

        const float hsA = prevH + curH + nextAH;
        const float hsB = curH + nextAH + nextBH;

        acc += row_loss(cA, cur,   pA, hsA, lane);
        acc += row_loss(cB, nextA, pB, hsB, lane);
    }

    acc *= NLN2;   // one scale: sum of w*log2(arg) -> sum of w*(-ln(arg))

    // ---- Block reduction: warp shuffle, then cross-warp via shared. ----
    #pragma unroll
    for (int off = 16; off > 0; off >>= 1)
        acc += __shfl_down_sync(FULLM, acc, off);

    __shared__ float swarp[NTHR / 32];
    if (lane == 0) swarp[warp] = acc;
    __syncthreads();
    if (tid == 0) {
        float v = 0.0f;
        #pragma unroll
        for (int i = 0; i < NTHR / 32; ++i) v += swarp[i];
        g_partials[blockIdx.x] = v;
    }

    // ---- Last-block fused finalize (deterministic order). ----
    __shared__ bool s_last;
    __threadfence();
    if (tid == 0) {
        unsigned int old = atomicAdd(&g_ticket, 1u);
        s_last = (old == NBLK - 1);
    }
    __syncthreads();

    if (s_last) {
        __shared__ double sd[NTHR];
        double s = 0.0;
        for (int i = tid; i < NBLK; i += NTHR)   // fixed order per thread
            s += (double)g_partials[i];
        sd[tid] = s;
        __syncthreads();
        #pragma unroll
        for (int stride = NTHR / 2; stride > 0; stride >>= 1) {
            if (tid < stride) sd[tid] += sd[tid + stride];
            __syncthreads();
        }
        if (tid == 0) {
            out[0] = (float)(sd[0] / (double)((size_t)Bd * Hd * Wd));
            g_ticket = 0;                        // reset for next launch/replay
        }
    }
}

extern "C" void kernel_launch(void* const* d_in, const int* in_sizes, int n_in,
                              void* d_out, int out_size)
{
    (void)in_sizes; (void)n_in; (void)out_size;
    const float* pred   = (const float*)d_in[0];
    const float* target = (const float*)d_in[1];
    float* out = (float*)d_out;

    bab_fused<<<NBLK, NTHR>>>(pred, target, out);
}

// round 16
// speedup vs baseline: 1.1194x; 1.1194x over previous
#include <cuda_runtime.h>
#include <math.h>

// Problem shape (fixed by setup_inputs): pred/target (32,1,1024,1024) f32.
#define Wd   1024
#define Hd   1024
#define Bd   32
#define RPB  16                       // rows per block (R8-proven granularity)
#define GRPS (Hd / RPB)               // 64 row-groups per image
#define NBLK (Bd * GRPS)              // 2048 blocks
#define NTHR 256                      // 8 warps * 128 cols = 1024 cols

#define FULLM 0xFFFFFFFFu
#define NLN2  (-0.69314718055994530942f)

__device__ float        g_partials[NBLK];
__device__ unsigned int g_ticket;     // zero-init; reset by last block

__device__ __forceinline__ float4 ldv(const float* p) {
    return *reinterpret_cast<const float4*>(p);
}

// Per-row contribution: Sum_i w_i * log2(1-|t_i-p_i|), w_i = 1+2*b_i.
// Binary mask: 3x3-window sum S in [0,9]; boundary b = min(S, 9-S, 1).
// Border rows/cols handled by DUPLICATING the edge cell (clamp), which
// preserves S==0 <=> all-zero and S==9 <=> all-one exactly.
// haloSum: vertical 3-sum of this lane's halo column (lane 0 = left neighbor
// col, lane 31 = right neighbor col); address clamped into the image so the
// border case degenerates to the thread's own edge colsum (exact identity).
__device__ __forceinline__ float row_loss(
    const float4 c, const float4 t, const float4 p,
    float haloSum, int lane)
{
    float l = __shfl_up_sync(FULLM, c.w, 1);
    float r = __shfl_down_sync(FULLM, c.x, 1);
    if (lane == 0)  l = haloSum;
    if (lane == 31) r = haloSum;

    const float S0 = l   + c.x + c.y;
    const float S1 = c.x + c.y + c.z;
    const float S2 = c.y + c.z + c.w;
    const float S3 = c.z + c.w + r;

    const float b0 = fminf(fminf(S0, 9.0f - S0), 1.0f);
    const float b1 = fminf(fminf(S1, 9.0f - S1), 1.0f);
    const float b2 = fminf(fminf(S2, 9.0f - S2), 1.0f);
    const float b3 = fminf(fminf(S3, 9.0f - S3), 1.0f);

    // arg = 1-|t-p| == (t ? p : 1-p) exactly; pred in (1e-6, 1-1e-6) => arg>0.
    float s;
    s  = fmaf(2.0f, b0, 1.0f) * __log2f(1.0f - fabsf(t.x - p.x));
    s += fmaf(2.0f, b1, 1.0f) * __log2f(1.0f - fabsf(t.y - p.y));
    s += fmaf(2.0f, b2, 1.0f) * __log2f(1.0f - fabsf(t.z - p.z));
    s += fmaf(2.0f, b3, 1.0f) * __log2f(1.0f - fabsf(t.w - p.w));
    return s;
}

__device__ __forceinline__ float4 v4add(float4 a, float4 b) {
    float4 r; r.x=a.x+b.x; r.y=a.y+b.y; r.z=a.z+b.z; r.w=a.w+b.w; return r;
}

__global__ __launch_bounds__(NTHR, 5)
void bab_fused(const float* __restrict__ pred, const float* __restrict__ target,
               float* __restrict__ out)
{
    const int tid  = threadIdx.x;
    const int lane = tid & 31;
    const int warp = tid >> 5;

    const int grp = blockIdx.x;
    const int img = grp / GRPS;
    const int y0  = (grp % GRPS) * RPB;

    const int x0 = warp * 128 + lane * 4;     // this thread's 4 columns

    // Merged halo: lane 0 -> left neighbor col, lane 31 -> right neighbor col.
    // Address clamped into the image (border lanes read their own edge col).
    int xH = (lane == 0) ? (warp * 128 - 1) : (warp * 128 + 128);
    xH = (xH < 0) ? 0 : ((xH > Wd - 1) ? (Wd - 1) : xH);

    const float* __restrict__ tBase = target + (size_t)img * Hd * Wd + (size_t)y0 * Wd;
    const float* __restrict__ pBase = pred   + (size_t)img * Hd * Wd + (size_t)y0 * Wd;

    const float* tRow  = tBase + x0;
    const float* pRow  = pBase + x0;
    const float* tHalo = tBase + xH;

    // prev row: y0-1, clamped to y0 at the top border (duplicate row).
    const int prevOff = (y0 > 0) ? -Wd : 0;

    float4 cur  = ldv(tRow);
    float4 prev = ldv(tRow + prevOff);
    float curH  = tHalo[0];
    float prevH = tHalo[prevOff];

    float acc = 0.0f;

    // 3 unconditional 4-row iterations (rows y0..y0+11): row y+4 <= y0+15 < Hd.
    #pragma unroll
    for (int it = 0; it < RPB / 4 - 1; ++it) {
        // Front batch: 4 target rows + first 2 pred rows + 4 halo scalars.
        const float4 n1 = ldv(tRow + Wd);
        const float4 n2 = ldv(tRow + 2 * Wd);
        const float4 n3 = ldv(tRow + 3 * Wd);
        const float4 n4 = ldv(tRow + 4 * Wd);
        const float4 p0 = ldv(pRow);
        const float4 p1 = ldv(pRow + Wd);
        const float h1 = tHalo[Wd];
        const float h2 = tHalo[2 * Wd];
        const float h3 = tHalo[3 * Wd];
        const float h4 = tHalo[4 * Wd];

        // Pairwise-shared vertical column sums (6 FADD/row).
        const float4 s01 = v4add(cur, n1);
        const float4 s23 = v4add(n2, n3);
        const float4 cA = v4add(prev, s01);   // rows y-1..y+1
        const float4 cB = v4add(s01, n2);     // rows y..y+2
        const float4 cC = v4add(n1, s23);     // rows y+1..y+3
        const float4 cD = v4add(s23, n4);     // rows y+2..y+4

        const float sp1 = curH + h1, sp2 = h2 + h3;
        const float hA = prevH + sp1;
        const float hB = sp1 + h2;
        const float hC = h1 + sp2;
        const float hD = sp2 + h4;

        acc += row_loss(cA, cur, p0, hA, lane);
        acc += row_loss(cB, n1,  p1, hB, lane);

        // Second pred batch mid-body (keeps in-flight regs within the cap).
        const float4 p2 = ldv(pRow + 2 * Wd);
        const float4 p3 = ldv(pRow + 3 * Wd);
        acc += row_loss(cC, n2, p2, hC, lane);
        acc += row_loss(cD, n3, p3, hD, lane);

        prev  = n3;  cur  = n4;
        prevH = h3;  curH = h4;

        tRow  += 4 * Wd;
        pRow  += 4 * Wd;
        tHalo += 4 * Wd;
    }

    // Final 4-row iteration (rows y0+12..y0+15): row y+4 exists unless this is
    // the last row-group of the image; then duplicate row y+3.
    {
        const int offB = (y0 + RPB < Hd) ? (4 * Wd) : (3 * Wd);

        const float4 n1 = ldv(tRow + Wd);
        const float4 n2 = ldv(tRow + 2 * Wd);
        const float4 n3 = ldv(tRow + 3 * Wd);
        const float4 n4 = ldv(tRow + offB);
        const float4 p0 = ldv(pRow);
        const float4 p1 = ldv(pRow + Wd);
        const float h1 = tHalo[Wd];
        const float h2 = tHalo[2 * Wd];
        const float h3 = tHalo[3 * Wd];
        const float h4 = tHalo[offB];

        const float4 s01 = v4add(cur, n1);
        const float4 s23 = v4add(n2, n3);
        const float4 cA = v4add(prev, s01);
        const float4 cB = v4add(s01, n2);
        const float4 cC = v4add(n1, s23);
        const float4 cD = v4add(s23, n4);

        const float sp1 = curH + h1, sp2 = h2 + h3;
        const float hA = prevH + sp1;
        const float hB = sp1 + h2;
        const float hC = h1 + sp2;
        const float hD = sp2 + h4;

        acc += row_loss(cA, cur, p0, hA, lane);
        acc += row_loss(cB, n1,  p1, hB, lane);

        const float4 p2 = ldv(pRow + 2 * Wd);
        const float4 p3 = ldv(pRow + 3 * Wd);
        acc += row_loss(cC, n2, p2, hC, lane);
        acc += row_loss(cD, n3, p3, hD, lane);
    }

    acc *= NLN2;   // one scale: sum of w*log2(arg) -> sum of w*(-ln(arg))

    // ---- Block reduction: warp shuffle, then cross-warp via shared. ----
    #pragma unroll
    for (int off = 16; off > 0; off >>= 1)
        acc += __shfl_down_sync(FULLM, acc, off);

    __shared__ float swarp[NTHR / 32];
    if (lane == 0) swarp[warp] = acc;
    __syncthreads();
    if (tid == 0) {
        float v = 0.0f;
        #pragma unroll
        for (int i = 0; i < NTHR / 32; ++i) v += swarp[i];
        g_partials[blockIdx.x] = v;
    }

    // ---- Last-block fused finalize (deterministic order). ----
    __shared__ bool s_last;
    __threadfence();
    if (tid == 0) {
        unsigned int old = atomicAdd(&g_ticket, 1u);
        s_last = (old == NBLK - 1);
    }
    __syncthreads();

    if (s_last) {
        __shared__ double sd[NTHR];
        double s = 0.0;
        for (int i = tid; i < NBLK; i += NTHR)   // fixed order per thread
            s += (double)g_partials[i];
        sd[tid] = s;
        __syncthreads();
        #pragma unroll
        for (int stride = NTHR / 2; stride > 0; stride >>= 1) {
            if (tid < stride) sd[tid] += sd[tid + stride];
            __syncthreads();
        }
        if (tid == 0) {
            out[0] = (float)(sd[0] / (double)((size_t)Bd * Hd * Wd));
            g_ticket = 0;                        // reset for next launch/replay
        }
    }
}

extern "C" void kernel_launch(void* const* d_in, const int* in_sizes, int n_in,
                              void* d_out, int out_size)
{
    (void)in_sizes; (void)n_in; (void)out_size;
    const float* pred   = (const float*)d_in[0];
    const float* target = (const float*)d_in[1];
    float* out = (float*)d_out;

    bab_fused<<<NBLK, NTHR>>>(pred, target, out);
}